// round 11
// baseline (speedup 1.0000x reference)
#include <cuda_runtime.h>
#include <cuda_bf16.h>
#include <cstdint>

// Inputs (metadata order):
//   d_in[0] : energy_readout            float32 [262144]
//   d_in[1] : atomic_numbers            int32   [8388608]
//   d_in[2] : atomic_subsystem_indices  int32   [8388608]  (sorted ascending)
//   d_in[3] : self_energies_tensor      float32 [100]
// Output: float32 [262144] = energy_readout + segment_sum(se[Z], seg_idx)

#define LUT_SIZE_MAX 128
#define CHUNK 8           // atoms per thread per iteration (32B per array)
#define TPB 256
#define NSTAGE 2
#define GRID_SEGSUM 896   // ~6 CTAs/SM residency (smem-limited)

__global__ void init_out_kernel(const float* __restrict__ e,
                                float* __restrict__ out, int n4) {
    int i = blockIdx.x * blockDim.x + threadIdx.x;
    if (i < n4) {
        reinterpret_cast<float4*>(out)[i] =
            reinterpret_cast<const float4*>(e)[i];
    }
}

__device__ __forceinline__ void cp_async16(uint32_t smem_addr, const void* gptr) {
    asm volatile("cp.async.cg.shared.global [%0], [%1], 16;\n"
                 :: "r"(smem_addr), "l"(gptr));
}
__device__ __forceinline__ void cp_commit() {
    asm volatile("cp.async.commit_group;\n" ::: "memory");
}
__device__ __forceinline__ void cp_wait1() {
    asm volatile("cp.async.wait_group 1;\n" ::: "memory");
}

__global__ void __launch_bounds__(TPB, 6)
self_energy_segsum_kernel(const int* __restrict__ zs,
                          const int* __restrict__ seg,
                          const float* __restrict__ se,
                          float* __restrict__ out,
                          int n_atoms, int n_se) {
    __shared__ float s_se[LUT_SIZE_MAX];
    // Per-thread private staging: buf[stage][array][thread][16B].
    // arrays: 0,1 = z lower/upper 16B; 2,3 = seg lower/upper 16B.
    __shared__ __align__(16) char buf[NSTAGE][4][TPB][16];

    for (int i = threadIdx.x; i < LUT_SIZE_MAX; i += blockDim.x)
        s_se[i] = (i < n_se) ? se[i] : 0.0f;
    __syncthreads();

    const int t = threadIdx.x;
    const int tid = blockIdx.x * TPB + t;
    const int stride = gridDim.x * TPB;
    const int n_chunks = n_atoms / CHUNK;

    // Shared-state-space addresses of this thread's 4 slots per stage.
    uint32_t sa[NSTAGE][4];
#pragma unroll
    for (int st = 0; st < NSTAGE; st++)
#pragma unroll
        for (int a = 0; a < 4; a++)
            sa[st][a] = (uint32_t)__cvta_generic_to_shared(&buf[st][a][t][0]);

    // ---- prologue: stage 0 <- chunk tid ----
    int c = tid;
    if (c < n_chunks) {
        const char* gz = (const char*)(zs + (long long)c * CHUNK);
        const char* gs = (const char*)(seg + (long long)c * CHUNK);
        cp_async16(sa[0][0], gz);
        cp_async16(sa[0][1], gz + 16);
        cp_async16(sa[0][2], gs);
        cp_async16(sa[0][3], gs + 16);
    }
    cp_commit();

    int st = 0;
    while (c < n_chunks) {
        // ---- prefetch next chunk into the other stage (async, fire & forget)
        int cn = c + stride;
        if (cn < n_chunks) {
            const char* gz = (const char*)(zs + (long long)cn * CHUNK);
            const char* gs = (const char*)(seg + (long long)cn * CHUNK);
            cp_async16(sa[st ^ 1][0], gz);
            cp_async16(sa[st ^ 1][1], gz + 16);
            cp_async16(sa[st ^ 1][2], gs);
            cp_async16(sa[st ^ 1][3], gs + 16);
        }
        cp_commit();
        cp_wait1();   // current stage complete; next stage still in flight

        // ---- consume current stage (thread-private smem; no syncs needed)
        int4 zv0 = *reinterpret_cast<const int4*>(&buf[st][0][t][0]);
        int4 zv1 = *reinterpret_cast<const int4*>(&buf[st][1][t][0]);
        int4 sv0 = *reinterpret_cast<const int4*>(&buf[st][2][t][0]);
        int4 sv1 = *reinterpret_cast<const int4*>(&buf[st][3][t][0]);

        int   s[8] = {sv0.x, sv0.y, sv0.z, sv0.w, sv1.x, sv1.y, sv1.z, sv1.w};
        int   z[8] = {zv0.x, zv0.y, zv0.z, zv0.w, zv1.x, zv1.y, zv1.z, zv1.w};
        int cur_seg = s[0];
        float run_sum = 0.0f;
#pragma unroll
        for (int k = 0; k < 8; k++) {
            if (s[k] != cur_seg) {
                atomicAdd(out + cur_seg, run_sum);   // interior run boundary
                cur_seg = s[k];
                run_sum = 0.0f;
            }
            run_sum += s_se[z[k]];
        }
        atomicAdd(out + cur_seg, run_sum);           // trailing run

        st ^= 1;
        c = cn;
    }

    // Tail atoms not covered by full chunks (none for 8388608, but be general)
    int tail_start = n_chunks * CHUNK;
    if (tid == 0 && tail_start < n_atoms) {
        int cs = -1; float rs = 0.0f;
        for (int i = tail_start; i < n_atoms; i++) {
            int sgv = seg[i];
            if (sgv != cs) { if (cs >= 0) atomicAdd(out + cs, rs); cs = sgv; rs = 0.0f; }
            rs += s_se[zs[i]];
        }
        if (cs >= 0) atomicAdd(out + cs, rs);
    }
}

extern "C" void kernel_launch(void* const* d_in, const int* in_sizes, int n_in,
                              void* d_out, int out_size) {
    const float* energy = (const float*)d_in[0];
    const int*   zs     = (const int*)d_in[1];
    const int*   seg    = (const int*)d_in[2];
    const float* se     = (const float*)d_in[3];
    float* out = (float*)d_out;

    int n_mol   = in_sizes[0];
    int n_atoms = in_sizes[1];
    int n_se    = in_sizes[3];

    // 1) out = energy_readout (d_out comes in poisoned). n_mol is 4-aligned.
    {
        int n4 = n_mol / 4;
        int blocks = (n4 + TPB - 1) / TPB;
        init_out_kernel<<<blocks, TPB>>>(energy, out, n4);
    }

    // 2) cp.async-staged segment sum: DRAM streaming decoupled from epilogue
    self_energy_segsum_kernel<<<GRID_SEGSUM, TPB>>>(zs, seg, se, out, n_atoms, n_se);
}

// round 12
// speedup vs baseline: 2.2182x; 2.2182x over previous
#include <cuda_runtime.h>
#include <cuda_bf16.h>

// Inputs (metadata order):
//   d_in[0] : energy_readout            float32 [262144]
//   d_in[1] : atomic_numbers            int32   [8388608]
//   d_in[2] : atomic_subsystem_indices  int32   [8388608]  (sorted ascending)
//   d_in[3] : self_energies_tensor      float32 [100]
// Output: float32 [262144] = energy_readout + segment_sum(se[Z], seg_idx)

#define LUT_SIZE_MAX 128
#define CHUNK 4           // atoms per thread (exactly one chunk per thread)
#define TPB 256

__global__ void init_out_kernel(const float* __restrict__ e,
                                float* __restrict__ out, int n4) {
    int i = blockIdx.x * blockDim.x + threadIdx.x;
    if (i < n4) {
        reinterpret_cast<float4*>(out)[i] =
            reinterpret_cast<const float4*>(e)[i];
    }
}

__global__ void __launch_bounds__(TPB, 8)
self_energy_segsum_kernel(const int* __restrict__ zs,
                          const int* __restrict__ seg,
                          const float* __restrict__ se,
                          float* __restrict__ out,
                          int n_atoms, int n_se) {
    __shared__ float s_se[LUT_SIZE_MAX];
    for (int i = threadIdx.x; i < LUT_SIZE_MAX; i += blockDim.x)
        s_se[i] = (i < n_se) ? se[i] : 0.0f;
    __syncthreads();

    long long base = (long long)(blockIdx.x * blockDim.x + threadIdx.x) * CHUNK;
    if (base >= n_atoms) return;

    if (base + CHUNK <= n_atoms) {
        // One 4-atom chunk per thread: 2 LDG.128, 4 LDS, short run loop.
        // CTA retires quickly; GigaThread backfill keeps SMs full of warps
        // that are in their load phase.
        int4 zv = *reinterpret_cast<const int4*>(zs + base);
        int4 sv = *reinterpret_cast<const int4*>(seg + base);

        int   s[4] = {sv.x, sv.y, sv.z, sv.w};
        int   z[4] = {zv.x, zv.y, zv.z, zv.w};

        int cur_seg = s[0];
        float run_sum = 0.0f;
#pragma unroll
        for (int k = 0; k < 4; k++) {
            if (s[k] != cur_seg) {
                atomicAdd(out + cur_seg, run_sum);   // interior run boundary
                cur_seg = s[k];
                run_sum = 0.0f;
            }
            run_sum += s_se[z[k]];
        }
        atomicAdd(out + cur_seg, run_sum);           // trailing run
    } else {
        // Tail safety (not hit for 8388608 atoms, but be general)
        int cs = -1; float rs = 0.0f;
        for (long long i = base; i < n_atoms; i++) {
            int s = seg[i];
            if (s != cs) { if (cs >= 0) atomicAdd(out + cs, rs); cs = s; rs = 0.0f; }
            rs += s_se[zs[i]];
        }
        if (cs >= 0) atomicAdd(out + cs, rs);
    }
}

extern "C" void kernel_launch(void* const* d_in, const int* in_sizes, int n_in,
                              void* d_out, int out_size) {
    const float* energy = (const float*)d_in[0];
    const int*   zs     = (const int*)d_in[1];
    const int*   seg    = (const int*)d_in[2];
    const float* se     = (const float*)d_in[3];
    float* out = (float*)d_out;

    int n_mol   = in_sizes[0];
    int n_atoms = in_sizes[1];
    int n_se    = in_sizes[3];

    // 1) out = energy_readout (d_out comes in poisoned). n_mol is 4-aligned.
    {
        int n4 = n_mol / 4;
        int blocks = (n4 + TPB - 1) / TPB;
        init_out_kernel<<<blocks, TPB>>>(energy, out, n4);
    }

    // 2) one-4-atom-chunk-per-thread segment sum with run-compressed atomics
    {
        long long threads_needed = ((long long)n_atoms + CHUNK - 1) / CHUNK;
        int blocks = (int)((threads_needed + TPB - 1) / TPB);
        self_energy_segsum_kernel<<<blocks, TPB>>>(zs, seg, se, out, n_atoms, n_se);
    }
}